// round 11
// baseline (speedup 1.0000x reference)
#include <cuda_runtime.h>
#include <cstdint>

#define N_EL     19
#define GPC      4                   // graphs per CTA block
#define ROWS     (N_EL * GPC)        // 76 valid rows
#define MPAD     80                  // 5 m16 tiles
#define N_GRAPHS 1800
#define C        128
#define NBLK     (N_GRAPHS / GPC)    // 450
#define GRID     (NBLK * 2)          // 900 (x column half)
#define NTHR     256

// smem map (bytes from dynamic base)
#define BOFF   0                     // B tf32: 4 k32-chunks x 128 rows x 128B
#define BCH    16384
#define XOFF   65536                 // X tf32: 4 chunks x 80 rows x 128B
#define XCH    10240
#define POFF   65536                 // P fp32 (reuses X): 76 rows x 264B
#define QOFF   0                     // Q fp32 (reuses B): 76 rows x 264B
#define PQSTR  264
#define AOFF   106496                // A 19x20 fp32
#define SMEM_BYTES 108032

// ===========================================================================
// helpers
// ===========================================================================
__device__ __forceinline__ uint32_t s2u(const void* p) {
    uint32_t a;
    asm("{ .reg .u64 t; cvta.to.shared.u64 t, %1; cvt.u32.u64 %0, t; }"
        : "=r"(a) : "l"(p));
    return a;
}
__device__ __forceinline__ uint32_t t32(float f) {
    uint32_t u;
    asm("cvt.rna.tf32.f32 %0, %1;" : "=r"(u) : "f"(f));
    return u;
}
__device__ __forceinline__ void sts16(uint32_t addr, uint4 v) {
    asm volatile("st.shared.v4.b32 [%0], {%1,%2,%3,%4};"
                 :: "r"(addr), "r"(v.x), "r"(v.y), "r"(v.z), "r"(v.w) : "memory");
}
__device__ __forceinline__ void sts8f(uint32_t addr, float a, float b) {
    asm volatile("st.shared.v2.f32 [%0], {%1,%2};"
                 :: "r"(addr), "f"(a), "f"(b) : "memory");
}
__device__ __forceinline__ uint4 lds16(uint32_t addr) {
    uint4 v;
    asm volatile("ld.shared.v4.b32 {%0,%1,%2,%3}, [%4];"
                 : "=r"(v.x), "=r"(v.y), "=r"(v.z), "=r"(v.w) : "r"(addr));
    return v;
}
__device__ __forceinline__ float lds4f(uint32_t addr) {
    float v;
    asm volatile("ld.shared.f32 %0, [%1];" : "=f"(v) : "r"(addr));
    return v;
}
__device__ __forceinline__ void mma_tf32(float* d, uint32_t a0, uint32_t a1,
                                         uint32_t a2, uint32_t a3,
                                         uint32_t b0, uint32_t b1) {
    asm volatile(
        "mma.sync.aligned.m16n8k8.row.col.f32.tf32.tf32.f32 "
        "{%0,%1,%2,%3}, {%4,%5,%6,%7}, {%8,%9}, {%0,%1,%2,%3};"
        : "+f"(d[0]), "+f"(d[1]), "+f"(d[2]), "+f"(d[3])
        : "r"(a0), "r"(a1), "r"(a2), "r"(a3), "r"(b0), "r"(b1));
}
// stage 16 k-values (k16 half 'h' of a k32 chunk) of one row:
// word(k) = (k&3)*8 + (k>>2); 16B granule g stored at g ^ (row & 7).
__device__ __forceinline__ void stage16(uint32_t rowbase, int row, int h,
                                        const float* f) {
#pragma unroll
    for (int cc = 0; cc < 4; cc++) {
        uint4 v = make_uint4(t32(f[cc]), t32(f[cc + 4]),
                             t32(f[cc + 8]), t32(f[cc + 12]));
        sts16(rowbase + (uint32_t)(((cc * 2 + h) ^ (row & 7)) << 4), v);
    }
}

// ===========================================================================
// Fused kernel, column-split:
//   CTA = (4 graphs, 64-col half nh). B = [Wrel rows nh*64.. | Wroot same].
//   [P|Q](76x64 each) = X(76x128) @ B^T ; out = A@P + Q + b (cols nh*64..)
// 256 threads, 8 warps; MMA: warp = n8-pair {wid (P), 8+wid (Q)}, all 80 rows.
// ===========================================================================
__global__ __launch_bounds__(NTHR, 2) void fused_kernel(
        const float* __restrict__ x,
        const float* __restrict__ ew,
        const float* __restrict__ Wrel,
        const float* __restrict__ brel,
        const float* __restrict__ Wroot,
        float* __restrict__ out) {
    extern __shared__ __align__(16) char smem[];
    const uint32_t sb = s2u(smem);
    float* As = (float*)(smem + AOFF);

    const int tid  = threadIdx.x;
    const int wid  = tid >> 5;
    const int lane = tid & 31;
    const int blk  = blockIdx.x >> 1;
    const int nh   = blockIdx.x & 1;

    // ---- build A (19x19) from edge weights
    for (int e = tid; e < N_EL * N_EL; e += NTHR) {
        const int j = e / N_EL, i = e % N_EL;
        float w = 0.0f;
        if (i != j) {
            const int r = (j < i) ? j : (j - 1);
            w = ew[i * (N_EL - 1) + r];
        }
        As[j * 20 + i] = w;
    }

    // ---- stage X: 640 units (row 0..79, chunk 0..3, half 0..1)
    for (int u = tid; u < MPAD * 8; u += NTHR) {
        const int row = u >> 3, c = (u >> 1) & 3, h = u & 1;
        float f[16];
        if (row < ROWS) {
            const float4* s4 = (const float4*)(x + (size_t)(blk * ROWS + row) * C
                                               + c * 32 + h * 16);
            *(float4*)&f[0]  = s4[0];
            *(float4*)&f[4]  = s4[1];
            *(float4*)&f[8]  = s4[2];
            *(float4*)&f[12] = s4[3];
        } else {
#pragma unroll
            for (int q = 0; q < 16; q++) f[q] = 0.0f;
        }
        stage16(sb + XOFF + (uint32_t)c * XCH + (uint32_t)row * 128u, row, h, f);
    }

    // ---- stage B: 1024 units (n 0..127: 64 Wrel rows then 64 Wroot rows)
    for (int u = tid; u < 128 * 8; u += NTHR) {
        const int n = u >> 3, c = (u >> 1) & 3, h = u & 1;
        const float* src = (n < 64) ? Wrel  + (size_t)(nh * 64 + n) * C
                                    : Wroot + (size_t)(nh * 64 + n - 64) * C;
        const float4* s4 = (const float4*)(src + c * 32 + h * 16);
        float f[16];
        *(float4*)&f[0]  = s4[0];
        *(float4*)&f[4]  = s4[1];
        *(float4*)&f[8]  = s4[2];
        *(float4*)&f[12] = s4[3];
        stage16(sb + BOFF + (uint32_t)c * BCH + (uint32_t)n * 128u, n, h, f);
    }
    __syncthreads();

    // ---- MMA burst: warp handles n8 tiles {wid -> P, 8+wid -> Q}, rows 0..79
    const int fr = lane >> 2;
    const int fc = lane & 3;

    float acc[5][2][4];
#pragma unroll
    for (int mt = 0; mt < 5; mt++)
#pragma unroll
        for (int q = 0; q < 2; q++)
#pragma unroll
            for (int v = 0; v < 4; v++)
                acc[mt][q][v] = 0.0f;

#pragma unroll
    for (int c = 0; c < 4; c++) {
#pragma unroll
        for (int s = 0; s < 2; s++) {
            const uint32_t gx = (uint32_t)(((fc * 2 + s) ^ fr) << 4);
            const int nrP = wid * 8 + fr;
            uint4 bP = lds16(sb + BOFF + (uint32_t)c * BCH
                             + (uint32_t)nrP * 128u + gx);
            uint4 bQ = lds16(sb + BOFF + (uint32_t)c * BCH
                             + (uint32_t)(nrP + 64) * 128u + gx);
#pragma unroll
            for (int mt = 0; mt < 5; mt++) {
                const int r0 = mt * 16 + fr;
                const uint32_t xb = sb + XOFF + (uint32_t)c * XCH
                                  + (uint32_t)(((fc * 2 + s) ^ (r0 & 7)) << 4);
                uint4 lo = lds16(xb + (uint32_t)r0 * 128u);
                uint4 hi = lds16(xb + (uint32_t)(r0 + 8) * 128u);
                mma_tf32(acc[mt][0], lo.x, hi.x, lo.y, hi.y, bP.x, bP.y);
                mma_tf32(acc[mt][0], lo.z, hi.z, lo.w, hi.w, bP.z, bP.w);
                mma_tf32(acc[mt][1], lo.x, hi.x, lo.y, hi.y, bQ.x, bQ.y);
                mma_tf32(acc[mt][1], lo.z, hi.z, lo.w, hi.w, bQ.z, bQ.w);
            }
        }
    }
    __syncthreads();   // X/B reads done -> safe to overwrite with P/Q

    // ---- write accumulators: P (local cols 0..63) / Q
#pragma unroll
    for (int mt = 0; mt < 5; mt++) {
#pragma unroll
        for (int q = 0; q < 2; q++) {
            const int col = wid * 8 + fc * 2;
            const uint32_t base = (q == 0 ? sb + POFF : sb + QOFF)
                                + (uint32_t)col * 4u;
#pragma unroll
            for (int half = 0; half < 2; half++) {
                const int r = mt * 16 + fr + half * 8;
                if (r < ROWS)
                    sts8f(base + (uint32_t)r * PQSTR,
                          acc[mt][q][half * 2], acc[mt][q][half * 2 + 1]);
            }
        }
    }
    __syncthreads();

    // ---- phase 2: 2 warps per graph, lane = 1 local col (0..63)
    {
        const int g   = wid >> 1;                // 0..3
        const int col = (wid & 1) * 32 + lane;   // 0..63
        const float bv = brel[nh * 64 + col];
        float p[N_EL];
#pragma unroll
        for (int i = 0; i < N_EL; i++)
            p[i] = lds4f(sb + POFF + (uint32_t)(g * N_EL + i) * PQSTR
                         + (uint32_t)col * 4u);
#pragma unroll
        for (int j = 0; j < N_EL; j++) {
            float o = lds4f(sb + QOFF + (uint32_t)(g * N_EL + j) * PQSTR
                            + (uint32_t)col * 4u) + bv;
#pragma unroll
            for (int i = 0; i < N_EL; i++)
                o = fmaf(As[j * 20 + i], p[i], o);
            out[(size_t)(blk * ROWS + g * N_EL + j) * C + nh * 64 + col] = o;
        }
    }
}

// ===========================================================================
// inputs (metadata order): x, edge_index, edge_weights, W_rel, b_rel, W_root
// ===========================================================================
extern "C" void kernel_launch(void* const* d_in, const int* in_sizes, int n_in,
                              void* d_out, int out_size) {
    const float* x     = (const float*)d_in[0];
    const float* ew    = (const float*)d_in[2];
    const float* Wrel  = (const float*)d_in[3];
    const float* brel  = (const float*)d_in[4];
    const float* Wroot = (const float*)d_in[5];
    float* out = (float*)d_out;

    cudaFuncSetAttribute(fused_kernel, cudaFuncAttributeMaxDynamicSharedMemorySize,
                         SMEM_BYTES);

    fused_kernel<<<GRID, NTHR, SMEM_BYTES>>>(x, ew, Wrel, brel, Wroot, out);
}

// round 12
// speedup vs baseline: 1.3600x; 1.3600x over previous
#include <cuda_runtime.h>
#include <cuda_fp16.h>
#include <cstdint>

#define N_EL     19
#define GPC      4                   // graphs per CTA
#define ROWS     76                  // valid rows
#define MPAD     80                  // 5 m16 tiles
#define N_GRAPHS 1800
#define C        128
#define GRID     (N_GRAPHS / GPC)    // 450
#define NTHR     256

// smem map (bytes from dynamic base)
#define BOFF   0                     // B fp16: 8 k16-blocks x 256 rows x 32B
#define BBLK   8192
#define XOFF   65536                 // X fp16: 8 blocks x 80 rows x 32B
#define XBLK   2560
#define QOFF   0                     // Q fp32 (reuses B region): 76 x 528B
#define POFF   40128                 // P fp32: 76 x 528B (ends 80256 < 86016)
#define PQSTR  528
#define AOFF   86016                 // A 19x20 fp32
#define SMEM_BYTES 87552             // x2 CTAs = 175104 <= 227KB

// ===========================================================================
// helpers
// ===========================================================================
__device__ __forceinline__ uint32_t s2u(const void* p) {
    uint32_t a;
    asm("{ .reg .u64 t; cvta.to.shared.u64 t, %1; cvt.u32.u64 %0, t; }"
        : "=r"(a) : "l"(p));
    return a;
}
__device__ __forceinline__ uint32_t h2(float a, float b) {
    __half2 t = __floats2half2_rn(a, b);     // a -> low half
    return *reinterpret_cast<uint32_t*>(&t);
}
__device__ __forceinline__ void sts16(uint32_t addr, uint32_t a, uint32_t b,
                                      uint32_t c, uint32_t d) {
    asm volatile("st.shared.v4.b32 [%0], {%1,%2,%3,%4};"
                 :: "r"(addr), "r"(a), "r"(b), "r"(c), "r"(d) : "memory");
}
__device__ __forceinline__ void sts8f(uint32_t addr, float a, float b) {
    asm volatile("st.shared.v2.f32 [%0], {%1,%2};"
                 :: "r"(addr), "f"(a), "f"(b) : "memory");
}
__device__ __forceinline__ float lds4f(uint32_t addr) {
    float v;
    asm volatile("ld.shared.f32 %0, [%1];" : "=f"(v) : "r"(addr));
    return v;
}
__device__ __forceinline__ void ldsm4(uint32_t addr, uint32_t& r0, uint32_t& r1,
                                      uint32_t& r2, uint32_t& r3) {
    asm volatile("ldmatrix.sync.aligned.m8n8.x4.shared.b16 {%0,%1,%2,%3}, [%4];"
                 : "=r"(r0), "=r"(r1), "=r"(r2), "=r"(r3) : "r"(addr));
}
__device__ __forceinline__ void mma_f16(float* d, uint32_t a0, uint32_t a1,
                                        uint32_t a2, uint32_t a3,
                                        uint32_t b0, uint32_t b1) {
    asm volatile(
        "mma.sync.aligned.m16n8k16.row.col.f32.f16.f16.f32 "
        "{%0,%1,%2,%3}, {%4,%5,%6,%7}, {%8,%9}, {%0,%1,%2,%3};"
        : "+f"(d[0]), "+f"(d[1]), "+f"(d[2]), "+f"(d[3])
        : "r"(a0), "r"(a1), "r"(a2), "r"(a3), "r"(b0), "r"(b1));
}
// 32B rows (16 fp16 = one k16 block), XOR-16B swizzle for conflict-free ldsm
__device__ __forceinline__ uint32_t rowoff(uint32_t r, uint32_t seg) {
    return (r * 32u + seg * 16u) ^ ((r & 4u) << 2);
}
// stage one (row, k16-block): 16 fp32 -> 16 fp16 as 2 x 16B granules
__device__ __forceinline__ void stage16h(uint32_t rowbase, int row,
                                         const float* f) {
    sts16(rowbase + rowoff((uint32_t)row, 0),
          h2(f[0], f[1]), h2(f[2], f[3]), h2(f[4], f[5]), h2(f[6], f[7]));
    sts16(rowbase + rowoff((uint32_t)row, 1),
          h2(f[8], f[9]), h2(f[10], f[11]), h2(f[12], f[13]), h2(f[14], f[15]));
}

// ===========================================================================
// Fused kernel (fp16 MMA):
//   per CTA (4 graphs): [P|Q](76x256) = X(76x128) @ [Wrel;Wroot]^T
//   then out = A @ P_g + Q_g + b  (fp32, A 19x19 shared from ew)
// 256 threads, 8 warps; warp = 32-col slab of the 256 N cols, all 80 rows.
// ===========================================================================
__global__ __launch_bounds__(NTHR, 2) void fused_kernel(
        const float* __restrict__ x,
        const float* __restrict__ ew,
        const float* __restrict__ Wrel,
        const float* __restrict__ brel,
        const float* __restrict__ Wroot,
        float* __restrict__ out) {
    extern __shared__ __align__(16) char smem[];
    const uint32_t sb = s2u(smem);
    float* As = (float*)(smem + AOFF);

    const int tid  = threadIdx.x;
    const int wid  = tid >> 5;
    const int lane = tid & 31;
    const int blk  = blockIdx.x;

    // ---- build A (19x19) from edge weights
    for (int e = tid; e < N_EL * N_EL; e += NTHR) {
        const int j = e / N_EL, i = e % N_EL;
        float w = 0.0f;
        if (i != j) {
            const int r = (j < i) ? j : (j - 1);
            w = ew[i * (N_EL - 1) + r];
        }
        As[j * 20 + i] = w;
    }

    // ---- stage X: 640 units (row 0..79, k16-block 0..7)
    for (int u = tid; u < MPAD * 8; u += NTHR) {
        const int row = u >> 3, c = u & 7;
        float f[16];
        if (row < ROWS) {
            const float4* s4 = (const float4*)(x + (size_t)(blk * ROWS + row) * C
                                               + c * 16);
            *(float4*)&f[0]  = s4[0];
            *(float4*)&f[4]  = s4[1];
            *(float4*)&f[8]  = s4[2];
            *(float4*)&f[12] = s4[3];
        } else {
#pragma unroll
            for (int q = 0; q < 16; q++) f[q] = 0.0f;
        }
        stage16h(sb + XOFF + (uint32_t)c * XBLK, row, f);
    }

    // ---- stage B: 2048 units (n 0..255: Wrel rows then Wroot rows)
    for (int u = tid; u < 256 * 8; u += NTHR) {
        const int n = u >> 3, c = u & 7;
        const float* src = (n < 128) ? Wrel  + (size_t)n * C
                                     : Wroot + (size_t)(n - 128) * C;
        const float4* s4 = (const float4*)(src + c * 16);
        float f[16];
        *(float4*)&f[0]  = s4[0];
        *(float4*)&f[4]  = s4[1];
        *(float4*)&f[8]  = s4[2];
        *(float4*)&f[12] = s4[3];
        stage16h(sb + BOFF + (uint32_t)c * BBLK, n, f);
    }
    __syncthreads();

    // ---- MMA: warp covers n-cols [wid*32, wid*32+32), rows 0..79, K=128
    const int tt = lane >> 3;
    const int rr = lane & 7;
    const int fr = lane >> 2;
    const int fc = lane & 3;
    // A frag: rows (tt&1)*8+rr, seg tt>>1 (+mt*16 rows = +512B)
    const uint32_t a_ld = rowoff((uint32_t)((tt & 1) * 8 + rr), (uint32_t)(tt >> 1));
    // B frag: rows (tt>>1)*8+rr, seg tt&1 (warp base + p*16 rows additive)
    const uint32_t b_ld = rowoff((uint32_t)((tt >> 1) * 8 + rr), (uint32_t)(tt & 1));

    float acc[5][4][4];
#pragma unroll
    for (int mt = 0; mt < 5; mt++)
#pragma unroll
        for (int n8 = 0; n8 < 4; n8++)
#pragma unroll
            for (int q = 0; q < 4; q++)
                acc[mt][n8][q] = 0.0f;

#pragma unroll
    for (int c = 0; c < 8; c++) {
        uint32_t nb[4][2];
#pragma unroll
        for (int p = 0; p < 2; p++) {
            uint32_t r0, r1, r2, r3;
            ldsm4(sb + BOFF + (uint32_t)c * BBLK + (uint32_t)(wid * 1024 + p * 512)
                  + b_ld, r0, r1, r2, r3);
            nb[p * 2 + 0][0] = r0; nb[p * 2 + 0][1] = r1;
            nb[p * 2 + 1][0] = r2; nb[p * 2 + 1][1] = r3;
        }
#pragma unroll
        for (int mt = 0; mt < 5; mt++) {
            uint32_t a0, a1, a2, a3;
            ldsm4(sb + XOFF + (uint32_t)c * XBLK + (uint32_t)(mt * 512) + a_ld,
                  a0, a1, a2, a3);
#pragma unroll
            for (int n8 = 0; n8 < 4; n8++)
                mma_f16(acc[mt][n8], a0, a1, a2, a3, nb[n8][0], nb[n8][1]);
        }
    }
    __syncthreads();   // X/B reads done -> safe to overwrite with P/Q

    // ---- writeback acc -> P (cols 0..127) / Q (cols 128..255), fp32
#pragma unroll
    for (int mt = 0; mt < 5; mt++) {
#pragma unroll
        for (int n8 = 0; n8 < 4; n8++) {
            const int colg = wid * 32 + n8 * 8 + fc * 2;
            const uint32_t base = (colg < 128)
                ? sb + POFF + (uint32_t)colg * 4u
                : sb + QOFF + (uint32_t)(colg - 128) * 4u;
#pragma unroll
            for (int half = 0; half < 2; half++) {
                const int r = mt * 16 + fr + half * 8;
                if (r < ROWS)
                    sts8f(base + (uint32_t)r * PQSTR,
                          acc[mt][n8][half * 2], acc[mt][n8][half * 2 + 1]);
            }
        }
    }
    __syncthreads();

    // ---- phase 2: 512 tasks (g 0..3, col 0..127), 2 per thread
    for (int t = tid; t < GPC * C; t += NTHR) {
        const int g = t >> 7, col = t & 127;
        const float bv = brel[col];
        float p[N_EL];
#pragma unroll
        for (int i = 0; i < N_EL; i++)
            p[i] = lds4f(sb + POFF + (uint32_t)(g * N_EL + i) * PQSTR
                         + (uint32_t)col * 4u);
#pragma unroll
        for (int j = 0; j < N_EL; j++) {
            float o = lds4f(sb + QOFF + (uint32_t)(g * N_EL + j) * PQSTR
                            + (uint32_t)col * 4u) + bv;
#pragma unroll
            for (int i = 0; i < N_EL; i++)
                o = fmaf(As[j * 20 + i], p[i], o);
            out[(size_t)(blk * ROWS + g * N_EL + j) * C + col] = o;
        }
    }
}

// ===========================================================================
// inputs (metadata order): x, edge_index, edge_weights, W_rel, b_rel, W_root
// ===========================================================================
extern "C" void kernel_launch(void* const* d_in, const int* in_sizes, int n_in,
                              void* d_out, int out_size) {
    const float* x     = (const float*)d_in[0];
    const float* ew    = (const float*)d_in[2];
    const float* Wrel  = (const float*)d_in[3];
    const float* brel  = (const float*)d_in[4];
    const float* Wroot = (const float*)d_in[5];
    float* out = (float*)d_out;

    cudaFuncSetAttribute(fused_kernel, cudaFuncAttributeMaxDynamicSharedMemorySize,
                         SMEM_BYTES);

    fused_kernel<<<GRID, NTHR, SMEM_BYTES>>>(x, ew, Wrel, brel, Wroot, out);
}

// round 13
// speedup vs baseline: 1.8959x; 1.3940x over previous
#include <cuda_runtime.h>
#include <cuda_fp16.h>
#include <cstdint>

#define N_EL     19
#define GPC      4                   // graphs per CTA
#define ROWS     76                  // valid rows
#define MPAD     80                  // 5 m16 tiles
#define N_GRAPHS 1800
#define C        128
#define GRID     (N_GRAPHS / GPC)    // 450
#define NTHR     256

// pre-converted B image: [Wrel;Wroot] fp16, swizzled smem layout, 64 KB
__device__ __align__(16) char g_Bh[65536];

// smem map (bytes from dynamic base)
#define BOFF   0                     // B fp16: 8 k16-blocks x 256 rows x 32B
#define BBLK   8192
#define XOFF   65536                 // X fp16: 8 blocks x 80 rows x 32B
#define XBLK   2560
#define QOFF   0                     // Q fp32 (reuses B region): 76 x 528B
#define POFF   40128                 // P fp32: 76 x 528B (ends 80256 < 86016)
#define PQSTR  528
#define AOFF   86016                 // A 19x20 fp32
#define SMEM_BYTES 87552             // x2 CTAs = 175104

// ===========================================================================
// helpers
// ===========================================================================
__device__ __forceinline__ uint32_t s2u(const void* p) {
    uint32_t a;
    asm("{ .reg .u64 t; cvta.to.shared.u64 t, %1; cvt.u32.u64 %0, t; }"
        : "=r"(a) : "l"(p));
    return a;
}
__device__ __forceinline__ uint32_t h2(float a, float b) {
    __half2 t = __floats2half2_rn(a, b);     // a -> low half
    return *reinterpret_cast<uint32_t*>(&t);
}
__device__ __forceinline__ void sts16(uint32_t addr, uint32_t a, uint32_t b,
                                      uint32_t c, uint32_t d) {
    asm volatile("st.shared.v4.b32 [%0], {%1,%2,%3,%4};"
                 :: "r"(addr), "r"(a), "r"(b), "r"(c), "r"(d) : "memory");
}
__device__ __forceinline__ void sts8f(uint32_t addr, float a, float b) {
    asm volatile("st.shared.v2.f32 [%0], {%1,%2};"
                 :: "r"(addr), "f"(a), "f"(b) : "memory");
}
__device__ __forceinline__ float lds4f(uint32_t addr) {
    float v;
    asm volatile("ld.shared.f32 %0, [%1];" : "=f"(v) : "r"(addr));
    return v;
}
__device__ __forceinline__ void ldsm4(uint32_t addr, uint32_t& r0, uint32_t& r1,
                                      uint32_t& r2, uint32_t& r3) {
    asm volatile("ldmatrix.sync.aligned.m8n8.x4.shared.b16 {%0,%1,%2,%3}, [%4];"
                 : "=r"(r0), "=r"(r1), "=r"(r2), "=r"(r3) : "r"(addr));
}
__device__ __forceinline__ void mma_f16(float* d, uint32_t a0, uint32_t a1,
                                        uint32_t a2, uint32_t a3,
                                        uint32_t b0, uint32_t b1) {
    asm volatile(
        "mma.sync.aligned.m16n8k16.row.col.f32.f16.f16.f32 "
        "{%0,%1,%2,%3}, {%4,%5,%6,%7}, {%8,%9}, {%0,%1,%2,%3};"
        : "+f"(d[0]), "+f"(d[1]), "+f"(d[2]), "+f"(d[3])
        : "r"(a0), "r"(a1), "r"(a2), "r"(a3), "r"(b0), "r"(b1));
}
__device__ __forceinline__ void cpa16(uint32_t dst, const void* src) {
    asm volatile("cp.async.cg.shared.global [%0], [%1], 16;"
                 :: "r"(dst), "l"(src) : "memory");
}
#define CP_COMMIT() asm volatile("cp.async.commit_group;" ::: "memory")
#define CP_WAIT0()  asm volatile("cp.async.wait_group 0;" ::: "memory")

// 32B rows (16 fp16 = one k16 block), XOR-16B swizzle for conflict-free ldsm
__device__ __forceinline__ uint32_t rowoff(uint32_t r, uint32_t seg) {
    return (r * 32u + seg * 16u) ^ ((r & 4u) << 2);
}
// stage one (row, k16-block): 16 fp32 -> 16 fp16 as 2 x 16B granules
__device__ __forceinline__ void stage16h(uint32_t rowbase, int row,
                                         const float* f) {
    sts16(rowbase + rowoff((uint32_t)row, 0),
          h2(f[0], f[1]), h2(f[2], f[3]), h2(f[4], f[5]), h2(f[6], f[7]));
    sts16(rowbase + rowoff((uint32_t)row, 1),
          h2(f[8], f[9]), h2(f[10], f[11]), h2(f[12], f[13]), h2(f[14], f[15]));
}

// ===========================================================================
// Kernel 0 (one-shot, tiny): build swizzled fp16 image of [Wrel;Wroot]
// ===========================================================================
__global__ __launch_bounds__(256) void conv_b(const float* __restrict__ Wrel,
                                              const float* __restrict__ Wroot) {
    const int u = blockIdx.x * 256 + threadIdx.x;   // 2048 units
    const int n = u >> 3, c = u & 7;
    const float* src = (n < 128) ? Wrel  + (size_t)n * C
                                 : Wroot + (size_t)(n - 128) * C;
    const float4* s4 = (const float4*)(src + c * 16);
    float f[16];
    *(float4*)&f[0]  = s4[0];
    *(float4*)&f[4]  = s4[1];
    *(float4*)&f[8]  = s4[2];
    *(float4*)&f[12] = s4[3];
    char* base = g_Bh + (size_t)c * BBLK;
    *(uint4*)(base + rowoff((uint32_t)n, 0)) =
        make_uint4(h2(f[0], f[1]), h2(f[2], f[3]), h2(f[4], f[5]), h2(f[6], f[7]));
    *(uint4*)(base + rowoff((uint32_t)n, 1)) =
        make_uint4(h2(f[8], f[9]), h2(f[10], f[11]), h2(f[12], f[13]),
                   h2(f[14], f[15]));
}

// ===========================================================================
// Fused kernel (fp16 MMA):
//   per CTA (4 graphs): [P|Q](76x256) = X(76x128) @ [Wrel;Wroot]^T
//   then out = A @ P_g + Q_g + b  (fp32, A 19x19 shared from ew)
// B staged via linear cp.async of the pre-converted image.
// 256 threads, 8 warps; warp = 32-col slab of the 256 N cols, all 80 rows.
// ===========================================================================
__global__ __launch_bounds__(NTHR, 2) void fused_kernel(
        const float* __restrict__ x,
        const float* __restrict__ ew,
        const float* __restrict__ brel,
        float* __restrict__ out) {
    extern __shared__ __align__(16) char smem[];
    const uint32_t sb = s2u(smem);
    float* As = (float*)(smem + AOFF);

    const int tid  = threadIdx.x;
    const int wid  = tid >> 5;
    const int lane = tid & 31;
    const int blk  = blockIdx.x;

    // ---- B staging: linear 64KB cp.async memcpy (issued first, overlaps below)
#pragma unroll
    for (int q = 0; q < 16; q++) {
        const uint32_t off = (uint32_t)(tid * 16 + q * 4096);
        cpa16(sb + BOFF + off, g_Bh + off);
    }
    CP_COMMIT();

    // ---- build A (19x19) from edge weights
    for (int e = tid; e < N_EL * N_EL; e += NTHR) {
        const int j = e / N_EL, i = e % N_EL;
        float w = 0.0f;
        if (i != j) {
            const int r = (j < i) ? j : (j - 1);
            w = ew[i * (N_EL - 1) + r];
        }
        As[j * 20 + i] = w;
    }

    // ---- stage X: 640 units (row 0..79, k16-block 0..7)
    for (int u = tid; u < MPAD * 8; u += NTHR) {
        const int row = u >> 3, c = u & 7;
        float f[16];
        if (row < ROWS) {
            const float4* s4 = (const float4*)(x + (size_t)(blk * ROWS + row) * C
                                               + c * 16);
            *(float4*)&f[0]  = s4[0];
            *(float4*)&f[4]  = s4[1];
            *(float4*)&f[8]  = s4[2];
            *(float4*)&f[12] = s4[3];
        } else {
#pragma unroll
            for (int q = 0; q < 16; q++) f[q] = 0.0f;
        }
        stage16h(sb + XOFF + (uint32_t)c * XBLK, row, f);
    }
    CP_WAIT0();
    __syncthreads();

    // ---- MMA: warp covers n-cols [wid*32, wid*32+32), rows 0..79, K=128
    const int tt = lane >> 3;
    const int rr = lane & 7;
    const int fr = lane >> 2;
    const int fc = lane & 3;
    const uint32_t a_ld = rowoff((uint32_t)((tt & 1) * 8 + rr), (uint32_t)(tt >> 1));
    const uint32_t b_ld = rowoff((uint32_t)((tt >> 1) * 8 + rr), (uint32_t)(tt & 1));

    float acc[5][4][4];
#pragma unroll
    for (int mt = 0; mt < 5; mt++)
#pragma unroll
        for (int n8 = 0; n8 < 4; n8++)
#pragma unroll
            for (int q = 0; q < 4; q++)
                acc[mt][n8][q] = 0.0f;

#pragma unroll
    for (int c = 0; c < 8; c++) {
        uint32_t nb[4][2];
#pragma unroll
        for (int p = 0; p < 2; p++) {
            uint32_t r0, r1, r2, r3;
            ldsm4(sb + BOFF + (uint32_t)c * BBLK + (uint32_t)(wid * 1024 + p * 512)
                  + b_ld, r0, r1, r2, r3);
            nb[p * 2 + 0][0] = r0; nb[p * 2 + 0][1] = r1;
            nb[p * 2 + 1][0] = r2; nb[p * 2 + 1][1] = r3;
        }
#pragma unroll
        for (int mt = 0; mt < 5; mt++) {
            uint32_t a0, a1, a2, a3;
            ldsm4(sb + XOFF + (uint32_t)c * XBLK + (uint32_t)(mt * 512) + a_ld,
                  a0, a1, a2, a3);
#pragma unroll
            for (int n8 = 0; n8 < 4; n8++)
                mma_f16(acc[mt][n8], a0, a1, a2, a3, nb[n8][0], nb[n8][1]);
        }
    }
    __syncthreads();   // X/B reads done -> safe to overwrite with P/Q

    // ---- writeback acc -> P (cols 0..127) / Q (cols 128..255), fp32
#pragma unroll
    for (int mt = 0; mt < 5; mt++) {
#pragma unroll
        for (int n8 = 0; n8 < 4; n8++) {
            const int colg = wid * 32 + n8 * 8 + fc * 2;
            const uint32_t base = (colg < 128)
                ? sb + POFF + (uint32_t)colg * 4u
                : sb + QOFF + (uint32_t)(colg - 128) * 4u;
#pragma unroll
            for (int half = 0; half < 2; half++) {
                const int r = mt * 16 + fr + half * 8;
                if (r < ROWS)
                    sts8f(base + (uint32_t)r * PQSTR,
                          acc[mt][n8][half * 2], acc[mt][n8][half * 2 + 1]);
            }
        }
    }
    __syncthreads();

    // ---- phase 2: 512 tasks (g 0..3, col 0..127), 2 per thread
    for (int t = tid; t < GPC * C; t += NTHR) {
        const int g = t >> 7, col = t & 127;
        const float bv = brel[col];
        float p[N_EL];
#pragma unroll
        for (int i = 0; i < N_EL; i++)
            p[i] = lds4f(sb + POFF + (uint32_t)(g * N_EL + i) * PQSTR
                         + (uint32_t)col * 4u);
#pragma unroll
        for (int j = 0; j < N_EL; j++) {
            float o = lds4f(sb + QOFF + (uint32_t)(g * N_EL + j) * PQSTR
                            + (uint32_t)col * 4u) + bv;
#pragma unroll
            for (int i = 0; i < N_EL; i++)
                o = fmaf(As[j * 20 + i], p[i], o);
            out[(size_t)(blk * ROWS + g * N_EL + j) * C + col] = o;
        }
    }
}

// ===========================================================================
// inputs (metadata order): x, edge_index, edge_weights, W_rel, b_rel, W_root
// ===========================================================================
extern "C" void kernel_launch(void* const* d_in, const int* in_sizes, int n_in,
                              void* d_out, int out_size) {
    const float* x     = (const float*)d_in[0];
    const float* ew    = (const float*)d_in[2];
    const float* Wrel  = (const float*)d_in[3];
    const float* brel  = (const float*)d_in[4];
    const float* Wroot = (const float*)d_in[5];
    float* out = (float*)d_out;

    cudaFuncSetAttribute(fused_kernel, cudaFuncAttributeMaxDynamicSharedMemorySize,
                         SMEM_BYTES);

    conv_b<<<8, 256>>>(Wrel, Wroot);
    fused_kernel<<<GRID, NTHR, SMEM_BYTES>>>(x, ew, brel, out);
}

// round 14
// speedup vs baseline: 2.1015x; 1.1085x over previous
#include <cuda_runtime.h>
#include <cuda_fp16.h>
#include <cstdint>

#define N_EL     19
#define GPC      4                   // graphs per CTA
#define ROWS     76                  // valid rows
#define MPAD     80                  // 5 m16 tiles
#define N_GRAPHS 1800
#define C        128
#define GRID     (N_GRAPHS / GPC)    // 450
#define NTHR     256

// pre-converted B image: [Wrel;Wroot] fp16, swizzled smem layout, 64 KB
__device__ __align__(16) char g_Bh[65536];

// smem map (bytes from dynamic base)
#define BOFF   0                     // B fp16: 8 k16-blocks x 256 rows x 32B
#define BBLK   8192
#define XOFF   65536                 // X fp16: 8 blocks x 80 rows x 32B
#define XBLK   2560
#define QOFF   0                     // Q fp32 (reuses B region): 76 x 528B
#define POFF   40128                 // P fp32: 76 x 528B (ends 80256 < 86016)
#define PQSTR  528
#define AOFF   86016                 // A 19x20 fp32
#define SMEM_BYTES 87552             // x2 CTAs = 175104

// ===========================================================================
// helpers
// ===========================================================================
__device__ __forceinline__ uint32_t s2u(const void* p) {
    uint32_t a;
    asm("{ .reg .u64 t; cvta.to.shared.u64 t, %1; cvt.u32.u64 %0, t; }"
        : "=r"(a) : "l"(p));
    return a;
}
__device__ __forceinline__ uint32_t h2(float a, float b) {
    __half2 t = __floats2half2_rn(a, b);     // a -> low half
    return *reinterpret_cast<uint32_t*>(&t);
}
__device__ __forceinline__ void sts16(uint32_t addr, uint32_t a, uint32_t b,
                                      uint32_t c, uint32_t d) {
    asm volatile("st.shared.v4.b32 [%0], {%1,%2,%3,%4};"
                 :: "r"(addr), "r"(a), "r"(b), "r"(c), "r"(d) : "memory");
}
__device__ __forceinline__ void sts8f(uint32_t addr, float a, float b) {
    asm volatile("st.shared.v2.f32 [%0], {%1,%2};"
                 :: "r"(addr), "f"(a), "f"(b) : "memory");
}
__device__ __forceinline__ float2 lds8f(uint32_t addr) {
    float2 v;
    asm volatile("ld.shared.v2.f32 {%0,%1}, [%2];"
                 : "=f"(v.x), "=f"(v.y) : "r"(addr));
    return v;
}
__device__ __forceinline__ float4 lds16f(uint32_t addr) {
    float4 v;
    asm volatile("ld.shared.v4.f32 {%0,%1,%2,%3}, [%4];"
                 : "=f"(v.x), "=f"(v.y), "=f"(v.z), "=f"(v.w) : "r"(addr));
    return v;
}
__device__ __forceinline__ void ldsm4(uint32_t addr, uint32_t& r0, uint32_t& r1,
                                      uint32_t& r2, uint32_t& r3) {
    asm volatile("ldmatrix.sync.aligned.m8n8.x4.shared.b16 {%0,%1,%2,%3}, [%4];"
                 : "=r"(r0), "=r"(r1), "=r"(r2), "=r"(r3) : "r"(addr));
}
__device__ __forceinline__ void mma_f16(float* d, uint32_t a0, uint32_t a1,
                                        uint32_t a2, uint32_t a3,
                                        uint32_t b0, uint32_t b1) {
    asm volatile(
        "mma.sync.aligned.m16n8k16.row.col.f32.f16.f16.f32 "
        "{%0,%1,%2,%3}, {%4,%5,%6,%7}, {%8,%9}, {%0,%1,%2,%3};"
        : "+f"(d[0]), "+f"(d[1]), "+f"(d[2]), "+f"(d[3])
        : "r"(a0), "r"(a1), "r"(a2), "r"(a3), "r"(b0), "r"(b1));
}
__device__ __forceinline__ void cpa16(uint32_t dst, const void* src) {
    asm volatile("cp.async.cg.shared.global [%0], [%1], 16;"
                 :: "r"(dst), "l"(src) : "memory");
}
#define CP_COMMIT() asm volatile("cp.async.commit_group;" ::: "memory")
#define CP_WAIT0()  asm volatile("cp.async.wait_group 0;" ::: "memory")

// 32B rows (16 fp16 = one k16 block), XOR-16B swizzle for conflict-free ldsm
__device__ __forceinline__ uint32_t rowoff(uint32_t r, uint32_t seg) {
    return (r * 32u + seg * 16u) ^ ((r & 4u) << 2);
}
// stage one (row, k16-block): 16 fp32 -> 16 fp16 as 2 x 16B granules
__device__ __forceinline__ void stage16h(uint32_t rowbase, int row,
                                         const float* f) {
    sts16(rowbase + rowoff((uint32_t)row, 0),
          h2(f[0], f[1]), h2(f[2], f[3]), h2(f[4], f[5]), h2(f[6], f[7]));
    sts16(rowbase + rowoff((uint32_t)row, 1),
          h2(f[8], f[9]), h2(f[10], f[11]), h2(f[12], f[13]), h2(f[14], f[15]));
}

// ===========================================================================
// Kernel 0 (one-shot, tiny): build swizzled fp16 image of [Wrel;Wroot]
// ===========================================================================
__global__ __launch_bounds__(256) void conv_b(const float* __restrict__ Wrel,
                                              const float* __restrict__ Wroot) {
    const int u = blockIdx.x * 256 + threadIdx.x;   // 2048 units
    const int n = u >> 3, c = u & 7;
    const float* src = (n < 128) ? Wrel  + (size_t)n * C
                                 : Wroot + (size_t)(n - 128) * C;
    const float4* s4 = (const float4*)(src + c * 16);
    float f[16];
    *(float4*)&f[0]  = s4[0];
    *(float4*)&f[4]  = s4[1];
    *(float4*)&f[8]  = s4[2];
    *(float4*)&f[12] = s4[3];
    char* base = g_Bh + (size_t)c * BBLK;
    *(uint4*)(base + rowoff((uint32_t)n, 0)) =
        make_uint4(h2(f[0], f[1]), h2(f[2], f[3]), h2(f[4], f[5]), h2(f[6], f[7]));
    *(uint4*)(base + rowoff((uint32_t)n, 1)) =
        make_uint4(h2(f[8], f[9]), h2(f[10], f[11]), h2(f[12], f[13]),
                   h2(f[14], f[15]));
}

// ===========================================================================
// Fused kernel (fp16 MMA):
//   per CTA (4 graphs): [P|Q](76x256) = X(76x128) @ [Wrel;Wroot]^T
//   then out = A @ P_g + Q_g + b  (fp32, A 19x19 shared from ew)
// B staged via linear cp.async of the pre-converted image.
// ===========================================================================
__global__ __launch_bounds__(NTHR, 2) void fused_kernel(
        const float* __restrict__ x,
        const float* __restrict__ ew,
        const float* __restrict__ brel,
        float* __restrict__ out) {
    extern __shared__ __align__(16) char smem[];
    const uint32_t sb = s2u(smem);
    float* As = (float*)(smem + AOFF);

    const int tid  = threadIdx.x;
    const int wid  = tid >> 5;
    const int lane = tid & 31;
    const int blk  = blockIdx.x;

    // ---- B staging: linear 64KB cp.async memcpy (issued first, overlaps below)
#pragma unroll
    for (int q = 0; q < 16; q++) {
        const uint32_t off = (uint32_t)(tid * 16 + q * 4096);
        cpa16(sb + BOFF + off, g_Bh + off);
    }
    CP_COMMIT();

    // ---- build A (19x19) from edge weights
    for (int e = tid; e < N_EL * N_EL; e += NTHR) {
        const int j = e / N_EL, i = e % N_EL;
        float w = 0.0f;
        if (i != j) {
            const int r = (j < i) ? j : (j - 1);
            w = ew[i * (N_EL - 1) + r];
        }
        As[j * 20 + i] = w;
    }

    // ---- stage X: 640 units (row 0..79, k16-block 0..7)
    for (int u = tid; u < MPAD * 8; u += NTHR) {
        const int row = u >> 3, c = u & 7;
        float f[16];
        if (row < ROWS) {
            const float4* s4 = (const float4*)(x + (size_t)(blk * ROWS + row) * C
                                               + c * 16);
            *(float4*)&f[0]  = s4[0];
            *(float4*)&f[4]  = s4[1];
            *(float4*)&f[8]  = s4[2];
            *(float4*)&f[12] = s4[3];
        } else {
#pragma unroll
            for (int q = 0; q < 16; q++) f[q] = 0.0f;
        }
        stage16h(sb + XOFF + (uint32_t)c * XBLK, row, f);
    }
    CP_WAIT0();
    __syncthreads();

    // ---- MMA: warp covers n-cols [wid*32, wid*32+32), rows 0..79, K=128
    const int tt = lane >> 3;
    const int rr = lane & 7;
    const int fr = lane >> 2;
    const int fc = lane & 3;
    const uint32_t a_ld = rowoff((uint32_t)((tt & 1) * 8 + rr), (uint32_t)(tt >> 1));
    const uint32_t b_ld = rowoff((uint32_t)((tt >> 1) * 8 + rr), (uint32_t)(tt & 1));

    float acc[5][4][4];
#pragma unroll
    for (int mt = 0; mt < 5; mt++)
#pragma unroll
        for (int n8 = 0; n8 < 4; n8++)
#pragma unroll
            for (int q = 0; q < 4; q++)
                acc[mt][n8][q] = 0.0f;

#pragma unroll
    for (int c = 0; c < 8; c++) {
        uint32_t nb[4][2];
#pragma unroll
        for (int p = 0; p < 2; p++) {
            uint32_t r0, r1, r2, r3;
            ldsm4(sb + BOFF + (uint32_t)c * BBLK + (uint32_t)(wid * 1024 + p * 512)
                  + b_ld, r0, r1, r2, r3);
            nb[p * 2 + 0][0] = r0; nb[p * 2 + 0][1] = r1;
            nb[p * 2 + 1][0] = r2; nb[p * 2 + 1][1] = r3;
        }
#pragma unroll
        for (int mt = 0; mt < 5; mt++) {
            uint32_t a0, a1, a2, a3;
            ldsm4(sb + XOFF + (uint32_t)c * XBLK + (uint32_t)(mt * 512) + a_ld,
                  a0, a1, a2, a3);
#pragma unroll
            for (int n8 = 0; n8 < 4; n8++)
                mma_f16(acc[mt][n8], a0, a1, a2, a3, nb[n8][0], nb[n8][1]);
        }
    }
    __syncthreads();   // X/B reads done -> safe to overwrite with P/Q

    // ---- writeback acc -> P (cols 0..127) / Q (cols 128..255), fp32
#pragma unroll
    for (int mt = 0; mt < 5; mt++) {
#pragma unroll
        for (int n8 = 0; n8 < 4; n8++) {
            const int colg = wid * 32 + n8 * 8 + fc * 2;
            const uint32_t base = (colg < 128)
                ? sb + POFF + (uint32_t)colg * 4u
                : sb + QOFF + (uint32_t)(colg - 128) * 4u;
#pragma unroll
            for (int half = 0; half < 2; half++) {
                const int r = mt * 16 + fr + half * 8;
                if (r < ROWS)
                    sts8f(base + (uint32_t)r * PQSTR,
                          acc[mt][n8][half * 2], acc[mt][n8][half * 2 + 1]);
            }
        }
    }
    __syncthreads();

    // ---- phase 2 (vectorized): 1 task/thread = (graph g, col pair cp)
    {
        const int g  = tid >> 6;                 // 0..3
        const int cp = (tid & 63) * 2;           // even col 0..126
        const float2 bv = *(const float2*)(brel + cp);
        float2 p[N_EL];
#pragma unroll
        for (int i = 0; i < N_EL; i++)
            p[i] = lds8f(sb + POFF + (uint32_t)(g * N_EL + i) * PQSTR
                         + (uint32_t)cp * 4u);
#pragma unroll
        for (int j = 0; j < N_EL; j++) {
            // As row j as 5 x float4 (20 floats; last lane of a4 is pad, unused)
            const uint32_t ab = sb + AOFF + (uint32_t)j * 80u;
            float a[20];
            *(float4*)&a[0]  = lds16f(ab);
            *(float4*)&a[4]  = lds16f(ab + 16u);
            *(float4*)&a[8]  = lds16f(ab + 32u);
            *(float4*)&a[12] = lds16f(ab + 48u);
            *(float4*)&a[16] = lds16f(ab + 64u);
            float2 o = lds8f(sb + QOFF + (uint32_t)(g * N_EL + j) * PQSTR
                             + (uint32_t)cp * 4u);
            o.x += bv.x; o.y += bv.y;
#pragma unroll
            for (int i = 0; i < N_EL; i++) {
                o.x = fmaf(a[i], p[i].x, o.x);
                o.y = fmaf(a[i], p[i].y, o.y);
            }
            *(float2*)(out + (size_t)(blk * ROWS + g * N_EL + j) * C + cp) = o;
        }
    }
}

// ===========================================================================
// inputs (metadata order): x, edge_index, edge_weights, W_rel, b_rel, W_root
// ===========================================================================
extern "C" void kernel_launch(void* const* d_in, const int* in_sizes, int n_in,
                              void* d_out, int out_size) {
    const float* x     = (const float*)d_in[0];
    const float* ew    = (const float*)d_in[2];
    const float* Wrel  = (const float*)d_in[3];
    const float* brel  = (const float*)d_in[4];
    const float* Wroot = (const float*)d_in[5];
    float* out = (float*)d_out;

    cudaFuncSetAttribute(fused_kernel, cudaFuncAttributeMaxDynamicSharedMemorySize,
                         SMEM_BYTES);

    conv_b<<<8, 256>>>(Wrel, Wroot);
    fused_kernel<<<GRID, NTHR, SMEM_BYTES>>>(x, ew, brel, out);
}